// round 4
// baseline (speedup 1.0000x reference)
#include <cuda_runtime.h>
#include <math.h>

#define PP 65160              // H*W
#define NGROUPS 8145          // PP/8 exact
#define FULLM 0xffffffffu

// scratch (point-major transposed x)
__device__ float  g_xsT[PP * 32];
__device__ float2 g_xvT2[PP * 16];

// ---------------- smem layout (floats) ----------------
#define WSS_OFF  0            // [(i*4+k)*32+o]        4096
#define WVS_OFF  4096         // [(i*4+k)*32+o]        2048
#define WSV_OFF  6144         // [(i*4+k)*16+o]        2048
#define WVV_OFF  8192         // [(i*4+k)*16+o]        1024
#define W1_OFF   9216         // [i*64+j]              2048
#define W2_OFF   11264        // [j*32+o]              2048
#define GW_OFF   13312        // [i*16+v]               512
#define BIAS_OFF 13824        // bs[32] b1[64] b2[32] gb[16] = 144
#define WARP_OFF 13968
#define WSTRIDE  1312
// per-warp offsets
#define O_PSS   0             // 64   [k][n]
#define O_PSV   64            // 128  [k][n][c]
#define O_PVS   192           // 128  [k][n][c]
#define O_PVV   320           // 256  [k][n][c][d]
#define O_ZSS   576           // 128  [i][k]
#define O_ZVS   704           // 64   [i][k]
#define O_ZSV   768           // 256  [c][i][k]
#define O_ZVV   1024          // 128  [c][i][k]
#define O_S     1152          // 32
#define O_H     1184          // 64
#define O_SO    1248          // 32
#define O_V     1280          // 32   [o*2+c]
#define SMEM_FLOATS (WARP_OFF + 8 * WSTRIDE)     // 24464
#define SMEM_BYTES  (SMEM_FLOATS * 4)            // 97856

__device__ __forceinline__ float gelu_exact(float x) { return x * normcdff(x); }

// -------------------------------------------------------------------------
// Transpose x_scalar (32,P)->(P,32) and x_vector (16,P,2)->(P,16) float2
// -------------------------------------------------------------------------
__global__ void transpose_x(const float* __restrict__ xs,
                            const float* __restrict__ xv) {
    const int p0 = blockIdx.x * 32;
    const int tx = threadIdx.x;   // 32
    const int ty = threadIdx.y;   // 8
    if (blockIdx.y == 0) {
        __shared__ float tile[32][33];
        #pragma unroll
        for (int r = ty; r < 32; r += 8) {
            int pp = p0 + tx;
            tile[r][tx] = (pp < PP) ? xs[r * PP + pp] : 0.f;
        }
        __syncthreads();
        #pragma unroll
        for (int r = ty; r < 32; r += 8) {
            int pp = p0 + r;
            if (pp < PP) g_xsT[pp * 32 + tx] = tile[tx][r];
        }
    } else {
        __shared__ float2 t2[16][33];
        const float2* xv2 = (const float2*)xv;   // [vch][p]
        #pragma unroll
        for (int r = ty; r < 16; r += 8) {
            int pp = p0 + tx;
            t2[r][tx] = (pp < PP) ? xv2[r * PP + pp] : make_float2(0.f, 0.f);
        }
        __syncthreads();
        const int tid = ty * 32 + tx;
        #pragma unroll
        for (int q = tid; q < 512; q += 256) {
            int i = q >> 4, v = q & 15;
            int pp = p0 + i;
            if (pp < PP) g_xvT2[pp * 16 + v] = t2[v][i];
        }
    }
}

// -------------------------------------------------------------------------
// Main: warp per point, 8 points per block-iteration, persistent grid.
// -------------------------------------------------------------------------
__global__ void __launch_bounds__(256, 2)
disco_main(const float* __restrict__ xs,  const float* __restrict__ xv,
           const int*   __restrict__ idx,
           const float* __restrict__ psi_ss, const float* __restrict__ psi_sv,
           const float* __restrict__ psi_vs, const float* __restrict__ psi_vv,
           const float* __restrict__ W_ss,  const float* __restrict__ W_vs,
           const float* __restrict__ W_sv,  const float* __restrict__ W_vv,
           const float* __restrict__ bias_s,
           const float* __restrict__ mlp_w1, const float* __restrict__ mlp_b1,
           const float* __restrict__ mlp_w2, const float* __restrict__ mlp_b2,
           const float* __restrict__ gate_w, const float* __restrict__ gate_b,
           float* __restrict__ out) {
    extern __shared__ float sm[];
    const int tid = threadIdx.x;

    // ---- stage W (transposed for conflict-free per-lane reads) ----
    for (int t = tid; t < 4096; t += 256) { int o = t >> 7, r = t & 127; sm[WSS_OFF + r * 32 + o] = W_ss[t]; }
    for (int t = tid; t < 2048; t += 256) { int o = t >> 6, r = t & 63;  sm[WVS_OFF + r * 32 + o] = W_vs[t]; }
    for (int t = tid; t < 2048; t += 256) { int o = t >> 7, r = t & 127; sm[WSV_OFF + r * 16 + o] = W_sv[t]; }
    for (int t = tid; t < 1024; t += 256) { int o = t >> 6, r = t & 63;  sm[WVV_OFF + r * 16 + o] = W_vv[t]; }
    for (int t = tid; t < 2048; t += 256) { int j = t >> 5, i = t & 31;  sm[W1_OFF + i * 64 + j]  = mlp_w1[t]; }
    for (int t = tid; t < 2048; t += 256) { int o = t >> 6, j = t & 63;  sm[W2_OFF + j * 32 + o]  = mlp_w2[t]; }
    for (int t = tid; t < 512;  t += 256) { int v = t >> 5, i = t & 31;  sm[GW_OFF + i * 16 + v]  = gate_w[t]; }
    if (tid < 32) sm[BIAS_OFF + tid]       = bias_s[tid];
    if (tid < 64) sm[BIAS_OFF + 32 + tid]  = mlp_b1[tid];
    if (tid < 32) sm[BIAS_OFF + 96 + tid]  = mlp_b2[tid];
    if (tid < 16) sm[BIAS_OFF + 128 + tid] = gate_b[tid];
    __syncthreads();

    const int warp = tid >> 5;
    const int lane = tid & 31;
    const int cc   = lane & 1;          // component for xv-holding lanes
    float* w = sm + WARP_OFF + warp * WSTRIDE;

    float4* Pss4 = (float4*)(w + O_PSS);
    float4* Psv4 = (float4*)(w + O_PSV);
    float4* Pvs4 = (float4*)(w + O_PVS);
    float4* Pvv4 = (float4*)(w + O_PVV);
    const float* Pvsf = w + O_PVS;
    const float* Pvvf = w + O_PVV;
    float4* Zss4 = (float4*)(w + O_ZSS);
    float4* Zvs4 = (float4*)(w + O_ZVS);
    float4* Zsv4 = (float4*)(w + O_ZSV);
    float4* Zvv4 = (float4*)(w + O_ZVV);
    float*  sS   = w + O_S;
    float*  sH   = w + O_H;
    float*  sSO  = w + O_SO;
    float*  sV   = w + O_V;

    const float* xvTf = (const float*)g_xvT2;
    const float4* gss = (const float4*)psi_ss;
    const float4* gsv = (const float4*)psi_sv;
    const float4* gvs = (const float4*)psi_vs;
    const float4* gvv = (const float4*)psi_vv;

    for (int grp = blockIdx.x; grp < NGROUPS; grp += gridDim.x) {
        const int p0 = grp * 8;
        const int p  = p0 + warp;

        // ---- gather neighbors (coalesced 128B per neighbor) ----
        int jreg = (lane < 16) ? idx[p * 16 + lane] : 0;
        float xsg[16], xvg[16];
        #pragma unroll
        for (int n = 0; n < 16; n++) {
            int jn = __shfl_sync(FULLM, jreg, n);
            xsg[n] = g_xsT[jn * 32 + lane];    // lane = scalar channel
            xvg[n] = xvTf[jn * 32 + lane];     // lane = vch*2 + comp
        }

        // ---- stage psi for this point ----
        if (lane < 16) Pss4[lane] = gss[((lane >> 2) * PP + p) * 4 + (lane & 3)];
        Psv4[lane] = gsv[((lane >> 3) * PP + p) * 8 + (lane & 7)];
        Pvs4[lane] = gvs[((lane >> 3) * PP + p) * 8 + (lane & 7)];
        Pvv4[lane]      = gvv[((lane >> 4) * PP + p) * 16 + (lane & 15)];
        Pvv4[lane + 32] = gvv[(((lane + 32) >> 4) * PP + p) * 16 + (lane & 15)];
        __syncwarp();

        // ---- z_ss: lane = i (0..31) ----
        {
            float zk[4];
            #pragma unroll
            for (int k = 0; k < 4; k++) {
                float a = 0.f;
                #pragma unroll
                for (int m = 0; m < 4; m++) {
                    float4 q = Pss4[k * 4 + m];
                    a += q.x * xsg[4*m] + q.y * xsg[4*m+1] + q.z * xsg[4*m+2] + q.w * xsg[4*m+3];
                }
                zk[k] = a;
            }
            Zss4[lane] = make_float4(zk[0], zk[1], zk[2], zk[3]);
        }
        // ---- z_sv: lane = i, accum (k,c) ----
        {
            float z0[4], z1[4];
            #pragma unroll
            for (int k = 0; k < 4; k++) {
                float a0 = 0.f, a1 = 0.f;
                #pragma unroll
                for (int m = 0; m < 8; m++) {
                    float4 q = Psv4[k * 8 + m];   // (n,c0)(n,c1)(n+1,c0)(n+1,c1)
                    a0 += q.x * xsg[2*m] + q.z * xsg[2*m+1];
                    a1 += q.y * xsg[2*m] + q.w * xsg[2*m+1];
                }
                z0[k] = a0; z1[k] = a1;
            }
            Zsv4[lane]      = make_float4(z0[0], z0[1], z0[2], z0[3]);
            Zsv4[32 + lane] = make_float4(z1[0], z1[1], z1[2], z1[3]);
        }
        // ---- z_vs: lane = (i=lane>>1, c=lane&1), reduce over c ----
        {
            float zk[4];
            #pragma unroll
            for (int k = 0; k < 4; k++) {
                float a = 0.f;
                #pragma unroll
                for (int n = 0; n < 16; n++)
                    a += Pvsf[(k * 16 + n) * 2 + cc] * xvg[n];
                a += __shfl_xor_sync(FULLM, a, 1);
                zk[k] = a;
            }
            if (cc == 0) Zvs4[lane >> 1] = make_float4(zk[0], zk[1], zk[2], zk[3]);
        }
        // ---- z_vv: lane = (i, d=lane&1), out (k,c), reduce over d ----
        {
            float z0[4], z1[4];
            #pragma unroll
            for (int k = 0; k < 4; k++) {
                float a0 = 0.f, a1 = 0.f;
                #pragma unroll
                for (int n = 0; n < 16; n++) {
                    float x = xvg[n];
                    a0 += Pvvf[((k * 16 + n) * 2 + 0) * 2 + cc] * x;
                    a1 += Pvvf[((k * 16 + n) * 2 + 1) * 2 + cc] * x;
                }
                a0 += __shfl_xor_sync(FULLM, a0, 1);
                a1 += __shfl_xor_sync(FULLM, a1, 1);
                z0[k] = a0; z1[k] = a1;
            }
            if (cc == 0) {
                Zvv4[lane >> 1]      = make_float4(z0[0], z0[1], z0[2], z0[3]);
                Zvv4[16 + (lane >> 1)] = make_float4(z1[0], z1[1], z1[2], z1[3]);
            }
        }
        __syncwarp();

        // ---- s[o]: lane = o ----
        float acc = sm[BIAS_OFF + lane];
        #pragma unroll 8
        for (int i = 0; i < 32; i++) {
            float4 z = Zss4[i];
            const float* wp = sm + WSS_OFF + i * 128 + lane;
            acc += wp[0] * z.x + wp[32] * z.y + wp[64] * z.z + wp[96] * z.w;
        }
        #pragma unroll 8
        for (int i = 0; i < 16; i++) {
            float4 z = Zvs4[i];
            const float* wp = sm + WVS_OFF + i * 128 + lane;
            acc += wp[0] * z.x + wp[32] * z.y + wp[64] * z.z + wp[96] * z.w;
        }
        float sg = gelu_exact(acc);
        sS[lane] = sg;

        // ---- v[o][c]: lane = c*16+o ----
        const int vc = lane >> 4, vo = lane & 15;
        float vacc = 0.f;
        #pragma unroll 8
        for (int i = 0; i < 32; i++) {
            float4 z = Zsv4[vc * 32 + i];
            const float* wp = sm + WSV_OFF + i * 64 + vo;
            vacc += wp[0] * z.x + wp[16] * z.y + wp[32] * z.z + wp[48] * z.w;
        }
        #pragma unroll 8
        for (int i = 0; i < 16; i++) {
            float4 z = Zvv4[vc * 16 + i];
            const float* wp = sm + WVV_OFF + i * 64 + vo;
            vacc += wp[0] * z.x + wp[16] * z.y + wp[32] * z.z + wp[48] * z.w;
        }
        __syncwarp();

        // ---- mlp hidden: lane computes j=lane and j=lane+32 ----
        {
            float a0 = sm[BIAS_OFF + 32 + lane];
            float a1 = sm[BIAS_OFF + 64 + lane];
            const float4* S4 = (const float4*)sS;
            #pragma unroll
            for (int i4 = 0; i4 < 8; i4++) {
                float4 s4 = S4[i4];
                const float* w1p = sm + W1_OFF + i4 * 256 + lane;
                a0 += w1p[0] * s4.x + w1p[64] * s4.y + w1p[128] * s4.z + w1p[192] * s4.w;
                const float* w1q = w1p + 32;
                a1 += w1q[0] * s4.x + w1q[64] * s4.y + w1q[128] * s4.z + w1q[192] * s4.w;
            }
            sH[lane]      = gelu_exact(a0);
            sH[lane + 32] = gelu_exact(a1);
        }
        __syncwarp();

        // ---- s_out[o]: lane = o ----
        {
            float a = sS[lane] + sm[BIAS_OFF + 96 + lane];
            const float4* H4 = (const float4*)sH;
            #pragma unroll
            for (int j4 = 0; j4 < 16; j4++) {
                float4 h4 = H4[j4];
                const float* w2p = sm + W2_OFF + j4 * 128 + lane;
                a += w2p[0] * h4.x + w2p[32] * h4.y + w2p[64] * h4.z + w2p[96] * h4.w;
            }
            sSO[lane] = a;
        }
        __syncwarp();

        // ---- gate + final v: lane = c*16+o ----
        {
            float g = sm[BIAS_OFF + 128 + vo];
            const float4* SO4 = (const float4*)sSO;
            #pragma unroll
            for (int i4 = 0; i4 < 8; i4++) {
                float4 s4 = SO4[i4];
                const float* gp = sm + GW_OFF + i4 * 64 + vo;
                g += gp[0] * s4.x + gp[16] * s4.y + gp[32] * s4.z + gp[48] * s4.w;
            }
            sV[vo * 2 + vc] = vacc * (1.f + g);
        }

        // ---- block epilogue: coalesced residual add + store ----
        __syncthreads();
        {
            int o = tid >> 3, wq = tid & 7;
            int pp = p0 + wq;
            const float* so = sm + WARP_OFF + wq * WSTRIDE + O_SO;
            out[o * PP + pp] = xs[o * PP + pp] + so[o];

            int ov = tid >> 4, r = tid & 15;
            int wv = r >> 1, c2 = r & 1;
            const float* vv = sm + WARP_OFF + wv * WSTRIDE + O_V;
            int voff = (ov * PP + p0 + wv) * 2 + c2;
            out[32 * PP + voff] = xv[voff] + vv[ov * 2 + c2];
        }
        __syncthreads();
    }
}

extern "C" void kernel_launch(void* const* d_in, const int* in_sizes, int n_in,
                              void* d_out, int out_size) {
    // Detect input ordering: dict order has idx (1,042,560) at slot 2;
    // signature order has psi_ss (4,170,240) there and idx last.
    const bool dictOrder = (in_sizes[2] == PP * 16);
    const float* xs = (const float*)d_in[0];
    const float* xv = (const float*)d_in[1];
    const int base = dictOrder ? 3 : 2;
    const float* pss  = (const float*)d_in[base + 0];
    const float* psv  = (const float*)d_in[base + 1];
    const float* pvs  = (const float*)d_in[base + 2];
    const float* pvv  = (const float*)d_in[base + 3];
    const float* wss  = (const float*)d_in[base + 4];
    const float* wvs  = (const float*)d_in[base + 5];
    const float* wsv  = (const float*)d_in[base + 6];
    const float* wvv  = (const float*)d_in[base + 7];
    const float* bs   = (const float*)d_in[base + 8];
    const float* w1   = (const float*)d_in[base + 9];
    const float* b1   = (const float*)d_in[base + 10];
    const float* w2   = (const float*)d_in[base + 11];
    const float* b2   = (const float*)d_in[base + 12];
    const float* gw   = (const float*)d_in[base + 13];
    const float* gb   = (const float*)d_in[base + 14];
    const int*   idx  = (const int*)(dictOrder ? d_in[2] : d_in[17]);

    cudaFuncSetAttribute(disco_main, cudaFuncAttributeMaxDynamicSharedMemorySize, SMEM_BYTES);

    dim3 tb(32, 8);
    transpose_x<<<dim3((PP + 31) / 32, 2), tb>>>(xs, xv);
    disco_main<<<296, 256, SMEM_BYTES>>>(xs, xv, idx, pss, psv, pvs, pvv,
                                         wss, wvs, wsv, wvv, bs,
                                         w1, b1, w2, b2, gw, gb,
                                         (float*)d_out);
}

// round 5
// speedup vs baseline: 1.2895x; 1.2895x over previous
#include <cuda_runtime.h>
#include <math.h>

#define PP 65160              // H*W
#define NG16 4073             // ceil(PP/16)
#define FULLM 0xffffffffu

// scratch (point-major transposed x)
__device__ float  g_xsT[PP * 32];
__device__ float2 g_xvT2[PP * 16];

// ---------------- smem layout (floats) ----------------
#define WSS_OFF  0            // [(i*4+k)*32+o]        4096
#define WVS_OFF  4096         // [(i*4+k)*32+o]        2048
#define WSV_OFF  6144         // [(i*4+k)*16+o]        2048
#define WVV_OFF  8192         // [(i*4+k)*16+o]        1024
#define W1_OFF   9216         // [i*64+j]              2048
#define W2_OFF   11264        // [j*32+o]              2048
#define GW_OFF   13312        // [i*16+v]               512
#define BIAS_OFF 13824        // bs[32] b1[64] b2[32] gb[16] = 144
#define WARP_OFF 13968
// per-warp region:
//   psi area (reused per point, aliased by S/H/SO/V in W phase):
#define O_PSS 0               // 64   [k][n]
#define O_PSV 64              // 128  [k][n][c]
#define O_PVS 192             // 136  [c][k][n], c-stride 68 (pad)
#define O_PVV 328             // 264  [d][k][n][c], d-stride 132 (pad)
#define PSI_END 592
//   SHV alias (per point q, base q*160): S+0(32) H+32(64) SO+96(32) V+128(32)
//   Z area: per point q at O_Z + q*592:
#define O_Z   592
//     ZSS +0   (128: [i] float4 over k)
//     ZVS +128 (64:  [i<16] float4)
//     ZSV +192 (264: [c][i] float4, c-stride 33 f4)
//     ZVV +456 (136: [c][i<16] float4, c-stride 17 f4)
#define WSTRIDE 1776          // 592 + 2*592
#define SMEM_FLOATS (WARP_OFF + 8 * WSTRIDE)   // 28176
#define SMEM_BYTES  (SMEM_FLOATS * 4)          // 112704

__device__ __forceinline__ float gelu_exact(float x) { return x * normcdff(x); }

// -------------------------------------------------------------------------
// Transpose x_scalar (32,P)->(P,32) and x_vector (16,P,2)->(P,16) float2
// -------------------------------------------------------------------------
__global__ void transpose_x(const float* __restrict__ xs,
                            const float* __restrict__ xv) {
    const int p0 = blockIdx.x * 32;
    const int tx = threadIdx.x;   // 32
    const int ty = threadIdx.y;   // 8
    if (blockIdx.y == 0) {
        __shared__ float tile[32][33];
        #pragma unroll
        for (int r = ty; r < 32; r += 8) {
            int pp = p0 + tx;
            tile[r][tx] = (pp < PP) ? xs[r * PP + pp] : 0.f;
        }
        __syncthreads();
        #pragma unroll
        for (int r = ty; r < 32; r += 8) {
            int pp = p0 + r;
            if (pp < PP) g_xsT[pp * 32 + tx] = tile[tx][r];
        }
    } else {
        __shared__ float2 t2[16][33];
        const float2* xv2 = (const float2*)xv;   // [vch][p]
        #pragma unroll
        for (int r = ty; r < 16; r += 8) {
            int pp = p0 + tx;
            t2[r][tx] = (pp < PP) ? xv2[r * PP + pp] : make_float2(0.f, 0.f);
        }
        __syncthreads();
        const int tid = ty * 32 + tx;
        #pragma unroll
        for (int q = tid; q < 512; q += 256) {
            int i = q >> 4, v = q & 15;
            int pp = p0 + i;
            if (pp < PP) g_xvT2[pp * 16 + v] = t2[v][i];
        }
    }
}

// -------------------------------------------------------------------------
// Main: warp handles TWO points (W smem reads amortized), 16 pts/block-iter.
// -------------------------------------------------------------------------
__global__ void __launch_bounds__(256, 2)
disco_main(const float* __restrict__ xs,  const float* __restrict__ xv,
           const int*   __restrict__ idx,
           const float* __restrict__ psi_ss, const float* __restrict__ psi_sv,
           const float* __restrict__ psi_vs, const float* __restrict__ psi_vv,
           const float* __restrict__ W_ss,  const float* __restrict__ W_vs,
           const float* __restrict__ W_sv,  const float* __restrict__ W_vv,
           const float* __restrict__ bias_s,
           const float* __restrict__ mlp_w1, const float* __restrict__ mlp_b1,
           const float* __restrict__ mlp_w2, const float* __restrict__ mlp_b2,
           const float* __restrict__ gate_w, const float* __restrict__ gate_b,
           float* __restrict__ out) {
    extern __shared__ float sm[];
    const int tid = threadIdx.x;

    // ---- stage W (transposed for conflict-free per-lane reads) ----
    for (int t = tid; t < 4096; t += 256) { int o = t >> 7, r = t & 127; sm[WSS_OFF + r * 32 + o] = W_ss[t]; }
    for (int t = tid; t < 2048; t += 256) { int o = t >> 6, r = t & 63;  sm[WVS_OFF + r * 32 + o] = W_vs[t]; }
    for (int t = tid; t < 2048; t += 256) { int o = t >> 7, r = t & 127; sm[WSV_OFF + r * 16 + o] = W_sv[t]; }
    for (int t = tid; t < 1024; t += 256) { int o = t >> 6, r = t & 63;  sm[WVV_OFF + r * 16 + o] = W_vv[t]; }
    for (int t = tid; t < 2048; t += 256) { int j = t >> 5, i = t & 31;  sm[W1_OFF + i * 64 + j]  = mlp_w1[t]; }
    for (int t = tid; t < 2048; t += 256) { int o = t >> 6, j = t & 63;  sm[W2_OFF + j * 32 + o]  = mlp_w2[t]; }
    for (int t = tid; t < 512;  t += 256) { int v = t >> 5, i = t & 31;  sm[GW_OFF + i * 16 + v]  = gate_w[t]; }
    if (tid < 32) sm[BIAS_OFF + tid]       = bias_s[tid];
    if (tid < 64) sm[BIAS_OFF + 32 + tid]  = mlp_b1[tid];
    if (tid < 32) sm[BIAS_OFF + 96 + tid]  = mlp_b2[tid];
    if (tid < 16) sm[BIAS_OFF + 128 + tid] = gate_b[tid];
    __syncthreads();

    const int warp = tid >> 5;
    const int lane = tid & 31;
    const int cc   = lane & 1;
    float* w = sm + WARP_OFF + warp * WSTRIDE;

    float4* Pss4  = (float4*)(w + O_PSS);
    float4* Psv4  = (float4*)(w + O_PSV);
    float4* Pvs4  = (float4*)(w + O_PVS);   // idx cc*17 + k*4 + m
    float4* Pvv4  = (float4*)(w + O_PVV);   // idx cc*33 + k*8 + m
    float2* PvsW2 = (float2*)(w + O_PVS);
    float2* PvvW2 = (float2*)(w + O_PVV);

    const float* xvTf = (const float*)g_xvT2;
    const float4* gss = (const float4*)psi_ss;
    const float4* gsv = (const float4*)psi_sv;
    const float4* gvs = (const float4*)psi_vs;
    const float4* gvv = (const float4*)psi_vv;

    for (int grp = blockIdx.x; grp < NG16; grp += gridDim.x) {
        const int p0 = grp * 16;

        // ================= z phase: two points sequentially =================
        #pragma unroll 1
        for (int q = 0; q < 2; q++) {
            const int p  = p0 + (warp << 1) + q;
            const int pc = (p < PP) ? p : (PP - 1);

            // gather neighbors (coalesced 128B per neighbor)
            int jreg = (lane < 16) ? idx[pc * 16 + lane] : 0;
            float xsg[16], xvg[16];
            #pragma unroll
            for (int n = 0; n < 16; n++) {
                int jn = __shfl_sync(FULLM, jreg, n);
                xsg[n] = g_xsT[jn * 32 + lane];
                xvg[n] = xvTf[jn * 32 + lane];
            }

            // stage psi (transposed/padded layouts)
            if (lane < 16) Pss4[lane] = gss[((lane >> 2) * PP + pc) * 4 + (lane & 3)];
            Psv4[lane] = gsv[((lane >> 3) * PP + pc) * 8 + (lane & 7)];
            {
                float4 f = gvs[((lane >> 3) * PP + pc) * 8 + (lane & 7)];
                PvsW2[lane]      = make_float2(f.x, f.z);   // c=0
                PvsW2[34 + lane] = make_float2(f.y, f.w);   // c=1 (float 68+)
            }
            #pragma unroll
            for (int it = 0; it < 2; it++) {
                int t = lane + it * 32;
                float4 f = gvv[((t >> 4) * PP + pc) * 16 + (t & 15)];
                PvvW2[t]      = make_float2(f.x, f.z);      // d=0
                PvvW2[66 + t] = make_float2(f.y, f.w);      // d=1 (float 132+)
            }
            __syncwarp();

            float* Zq = w + O_Z + q * 592;
            float4* Zss4 = (float4*)(Zq + 0);
            float4* Zvs4 = (float4*)(Zq + 128);
            float4* Zsv4 = (float4*)(Zq + 192);   // c-stride 33 f4
            float4* Zvv4 = (float4*)(Zq + 456);   // c-stride 17 f4

            // z_ss: lane = i
            {
                float zk[4];
                #pragma unroll
                for (int k = 0; k < 4; k++) {
                    float a = 0.f;
                    #pragma unroll
                    for (int m = 0; m < 4; m++) {
                        float4 qq = Pss4[k * 4 + m];
                        a += qq.x * xsg[4*m] + qq.y * xsg[4*m+1] + qq.z * xsg[4*m+2] + qq.w * xsg[4*m+3];
                    }
                    zk[k] = a;
                }
                Zss4[lane] = make_float4(zk[0], zk[1], zk[2], zk[3]);
            }
            // z_sv: lane = i, outputs (k,c)
            {
                float z0[4], z1[4];
                #pragma unroll
                for (int k = 0; k < 4; k++) {
                    float a0 = 0.f, a1 = 0.f;
                    #pragma unroll
                    for (int m = 0; m < 8; m++) {
                        float4 qq = Psv4[k * 8 + m];
                        a0 += qq.x * xsg[2*m] + qq.z * xsg[2*m+1];
                        a1 += qq.y * xsg[2*m] + qq.w * xsg[2*m+1];
                    }
                    z0[k] = a0; z1[k] = a1;
                }
                Zsv4[lane]      = make_float4(z0[0], z0[1], z0[2], z0[3]);
                Zsv4[33 + lane] = make_float4(z1[0], z1[1], z1[2], z1[3]);
            }
            // z_vs: lane = (i=lane>>1, c=cc), float4 psi reads, reduce over c
            {
                float zk[4];
                #pragma unroll
                for (int k = 0; k < 4; k++) {
                    float a = 0.f;
                    #pragma unroll
                    for (int m = 0; m < 4; m++) {
                        float4 qq = Pvs4[cc * 17 + k * 4 + m];
                        a += qq.x * xvg[4*m] + qq.y * xvg[4*m+1] + qq.z * xvg[4*m+2] + qq.w * xvg[4*m+3];
                    }
                    a += __shfl_xor_sync(FULLM, a, 1);
                    zk[k] = a;
                }
                if (cc == 0) Zvs4[lane >> 1] = make_float4(zk[0], zk[1], zk[2], zk[3]);
            }
            // z_vv: lane = (i, d=cc), float4 psi reads, outputs (k,c), reduce d
            {
                float z0[4], z1[4];
                #pragma unroll
                for (int k = 0; k < 4; k++) {
                    float a0 = 0.f, a1 = 0.f;
                    #pragma unroll
                    for (int m = 0; m < 8; m++) {
                        float4 qq = Pvv4[cc * 33 + k * 8 + m];  // (n,c0)(n,c1)(n+1,c0)(n+1,c1)
                        a0 += qq.x * xvg[2*m] + qq.z * xvg[2*m+1];
                        a1 += qq.y * xvg[2*m] + qq.w * xvg[2*m+1];
                    }
                    a0 += __shfl_xor_sync(FULLM, a0, 1);
                    a1 += __shfl_xor_sync(FULLM, a1, 1);
                    z0[k] = a0; z1[k] = a1;
                }
                if (cc == 0) {
                    Zvv4[lane >> 1]      = make_float4(z0[0], z0[1], z0[2], z0[3]);
                    Zvv4[17 + (lane >> 1)] = make_float4(z1[0], z1[1], z1[2], z1[3]);
                }
            }
            __syncwarp();
        }

        // ================= W phase: both points share W reads ===============
        const float* ZA = w + O_Z;
        const float* ZB = w + O_Z + 592;
        const float4* ZssA4 = (const float4*)(ZA + 0);
        const float4* ZssB4 = (const float4*)(ZB + 0);
        const float4* ZvsA4 = (const float4*)(ZA + 128);
        const float4* ZvsB4 = (const float4*)(ZB + 128);
        const float4* ZsvA4 = (const float4*)(ZA + 192);
        const float4* ZsvB4 = (const float4*)(ZB + 192);
        const float4* ZvvA4 = (const float4*)(ZA + 456);
        const float4* ZvvB4 = (const float4*)(ZB + 456);
        float* SA  = w + 0;    float* SB  = w + 160;
        float* HA  = w + 32;   float* HB  = w + 192;
        float* SOA = w + 96;   float* SOB = w + 256;
        float* VA  = w + 128;  float* VB  = w + 288;

        // s[o]: lane = o
        float accA = sm[BIAS_OFF + lane];
        float accB = accA;
        #pragma unroll 8
        for (int i = 0; i < 32; i++) {
            const float* wp = sm + WSS_OFF + i * 128 + lane;
            float w0 = wp[0], w1 = wp[32], w2 = wp[64], w3 = wp[96];
            float4 zA = ZssA4[i], zB = ZssB4[i];
            accA += w0 * zA.x + w1 * zA.y + w2 * zA.z + w3 * zA.w;
            accB += w0 * zB.x + w1 * zB.y + w2 * zB.z + w3 * zB.w;
        }
        #pragma unroll 8
        for (int i = 0; i < 16; i++) {
            const float* wp = sm + WVS_OFF + i * 128 + lane;
            float w0 = wp[0], w1 = wp[32], w2 = wp[64], w3 = wp[96];
            float4 zA = ZvsA4[i], zB = ZvsB4[i];
            accA += w0 * zA.x + w1 * zA.y + w2 * zA.z + w3 * zA.w;
            accB += w0 * zB.x + w1 * zB.y + w2 * zB.z + w3 * zB.w;
        }
        float sgA = gelu_exact(accA);
        float sgB = gelu_exact(accB);
        SA[lane] = sgA;
        SB[lane] = sgB;

        // v[o][c]: lane = c*16+o
        const int vc = lane >> 4, vo = lane & 15;
        float vaccA = 0.f, vaccB = 0.f;
        #pragma unroll 8
        for (int i = 0; i < 32; i++) {
            const float* wp = sm + WSV_OFF + i * 64 + vo;
            float w0 = wp[0], w1 = wp[16], w2 = wp[32], w3 = wp[48];
            float4 zA = ZsvA4[vc * 33 + i], zB = ZsvB4[vc * 33 + i];
            vaccA += w0 * zA.x + w1 * zA.y + w2 * zA.z + w3 * zA.w;
            vaccB += w0 * zB.x + w1 * zB.y + w2 * zB.z + w3 * zB.w;
        }
        #pragma unroll 8
        for (int i = 0; i < 16; i++) {
            const float* wp = sm + WVV_OFF + i * 64 + vo;
            float w0 = wp[0], w1 = wp[16], w2 = wp[32], w3 = wp[48];
            float4 zA = ZvvA4[vc * 17 + i], zB = ZvvB4[vc * 17 + i];
            vaccA += w0 * zA.x + w1 * zA.y + w2 * zA.z + w3 * zA.w;
            vaccB += w0 * zB.x + w1 * zB.y + w2 * zB.z + w3 * zB.w;
        }
        __syncwarp();

        // mlp hidden: lane computes j=lane and j=lane+32, both points
        {
            float b0 = sm[BIAS_OFF + 32 + lane];
            float b1 = sm[BIAS_OFF + 64 + lane];
            float a0A = b0, a1A = b1, a0B = b0, a1B = b1;
            const float4* S4A = (const float4*)SA;
            const float4* S4B = (const float4*)SB;
            #pragma unroll
            for (int i4 = 0; i4 < 8; i4++) {
                float4 sA = S4A[i4], sB = S4B[i4];
                const float* w1p = sm + W1_OFF + i4 * 256 + lane;
                float u0 = w1p[0], u1 = w1p[64], u2 = w1p[128], u3 = w1p[192];
                a0A += u0 * sA.x + u1 * sA.y + u2 * sA.z + u3 * sA.w;
                a0B += u0 * sB.x + u1 * sB.y + u2 * sB.z + u3 * sB.w;
                const float* w1q = w1p + 32;
                float q0 = w1q[0], q1 = w1q[64], q2 = w1q[128], q3 = w1q[192];
                a1A += q0 * sA.x + q1 * sA.y + q2 * sA.z + q3 * sA.w;
                a1B += q0 * sB.x + q1 * sB.y + q2 * sB.z + q3 * sB.w;
            }
            HA[lane]      = gelu_exact(a0A);
            HA[lane + 32] = gelu_exact(a1A);
            HB[lane]      = gelu_exact(a0B);
            HB[lane + 32] = gelu_exact(a1B);
        }
        __syncwarp();

        // s_out[o]: lane = o
        {
            float aA = sgA + sm[BIAS_OFF + 96 + lane];
            float aB = sgB + sm[BIAS_OFF + 96 + lane];
            const float4* H4A = (const float4*)HA;
            const float4* H4B = (const float4*)HB;
            #pragma unroll 8
            for (int j4 = 0; j4 < 16; j4++) {
                float4 hA = H4A[j4], hB = H4B[j4];
                const float* w2p = sm + W2_OFF + j4 * 128 + lane;
                float u0 = w2p[0], u1 = w2p[32], u2 = w2p[64], u3 = w2p[96];
                aA += u0 * hA.x + u1 * hA.y + u2 * hA.z + u3 * hA.w;
                aB += u0 * hB.x + u1 * hB.y + u2 * hB.z + u3 * hB.w;
            }
            SOA[lane] = aA;
            SOB[lane] = aB;
        }
        __syncwarp();

        // gate + final v: lane = c*16+o
        {
            float gA = sm[BIAS_OFF + 128 + vo];
            float gB = gA;
            const float4* SO4A = (const float4*)SOA;
            const float4* SO4B = (const float4*)SOB;
            #pragma unroll
            for (int i4 = 0; i4 < 8; i4++) {
                float4 sA = SO4A[i4], sB = SO4B[i4];
                const float* gp = sm + GW_OFF + i4 * 64 + vo;
                float u0 = gp[0], u1 = gp[16], u2 = gp[32], u3 = gp[48];
                gA += u0 * sA.x + u1 * sA.y + u2 * sA.z + u3 * sA.w;
                gB += u0 * sB.x + u1 * sB.y + u2 * sB.z + u3 * sB.w;
            }
            VA[vo * 2 + vc] = vaccA * (1.f + gA);
            VB[vo * 2 + vc] = vaccB * (1.f + gB);
        }

        // ================= block epilogue: coalesced stores =================
        __syncthreads();
        #pragma unroll
        for (int rep = 0; rep < 2; rep++) {
            int qi = rep * 256 + tid;
            // scalar: 32 ch x 16 pts
            int o = qi >> 4, lp = qi & 15;
            int pp = p0 + lp;
            if (pp < PP) {
                const float* so = sm + WARP_OFF + (lp >> 1) * WSTRIDE + (lp & 1) * 160 + 96;
                out[o * PP + pp] = xs[o * PP + pp] + so[o];
            }
            // vector: 16 ch x 16 pts x 2 comp
            int v = qi >> 5, r = qi & 31;
            int lpv = r >> 1, c2 = r & 1;
            int ppv = p0 + lpv;
            if (ppv < PP) {
                const float* vv = sm + WARP_OFF + (lpv >> 1) * WSTRIDE + (lpv & 1) * 160 + 128;
                int voff = (v * PP + ppv) * 2 + c2;
                out[32 * PP + voff] = xv[voff] + vv[v * 2 + c2];
            }
        }
        __syncthreads();
    }
}

extern "C" void kernel_launch(void* const* d_in, const int* in_sizes, int n_in,
                              void* d_out, int out_size) {
    // Detect input ordering: dict order has idx (1,042,560) at slot 2.
    const bool dictOrder = (in_sizes[2] == PP * 16);
    const float* xs = (const float*)d_in[0];
    const float* xv = (const float*)d_in[1];
    const int base = dictOrder ? 3 : 2;
    const float* pss  = (const float*)d_in[base + 0];
    const float* psv  = (const float*)d_in[base + 1];
    const float* pvs  = (const float*)d_in[base + 2];
    const float* pvv  = (const float*)d_in[base + 3];
    const float* wss  = (const float*)d_in[base + 4];
    const float* wvs  = (const float*)d_in[base + 5];
    const float* wsv  = (const float*)d_in[base + 6];
    const float* wvv  = (const float*)d_in[base + 7];
    const float* bs   = (const float*)d_in[base + 8];
    const float* w1   = (const float*)d_in[base + 9];
    const float* b1   = (const float*)d_in[base + 10];
    const float* w2   = (const float*)d_in[base + 11];
    const float* b2   = (const float*)d_in[base + 12];
    const float* gw   = (const float*)d_in[base + 13];
    const float* gb   = (const float*)d_in[base + 14];
    const int*   idx  = (const int*)(dictOrder ? d_in[2] : d_in[17]);

    cudaFuncSetAttribute(disco_main, cudaFuncAttributeMaxDynamicSharedMemorySize, SMEM_BYTES);

    dim3 tb(32, 8);
    transpose_x<<<dim3((PP + 31) / 32, 2), tb>>>(xs, xv);
    disco_main<<<296, 256, SMEM_BYTES>>>(xs, xv, idx, pss, psv, pvs, pvv,
                                         wss, wvs, wsv, wvv, bs,
                                         w1, b1, w2, b2, gw, gb,
                                         (float*)d_out);
}

// round 6
// speedup vs baseline: 1.5320x; 1.1880x over previous
#include <cuda_runtime.h>
#include <math.h>

#define PP 65160              // H*W
#define NG24 2715             // PP/24 exact
#define FULLM 0xffffffffu

// scratch (point-major transposed x)
__device__ float  g_xsT[PP * 32];
__device__ float2 g_xvT2[PP * 16];

// ---------------- smem layout ----------------
// W area (float4 units): WSS 0..1024 [i*32+o], WVS 1024..1536 [i*32+o],
// WSV 1536..2048 [i*16+o], WVV 2048..2304 [i*16+o], W1 2304..2816 [i4*64+j],
// W2 2816..3328 [j4*32+o], GW 3328..3456 [i4*16+v].
// BIAS (floats) at 13824: bs[32] b1[64] b2[32] gb[16].
#define BIAS_OFF 13824
#define WARP_OFF 13968        // floats
#define WSTRIDE  2368         // floats = 4 * 592
// Per-point slot (592 floats), dual use:
//  psi-stage:  PSS +0(64), PSV +64(128), PVS +192(136, c-stride 68), PVV +328(264, d-stride 132)
//  z:          Zss +0(128), Zvs +128(64), Zsv +192(264, c-stride 33 f4), Zvv +456(136, c-stride 17 f4)
//  outputs:    S +0(32), H +32(64), SO +96(32), V +128(32)
#define SMEM_FLOATS (WARP_OFF + 6 * WSTRIDE)   // 28176
#define SMEM_BYTES  (SMEM_FLOATS * 4)          // 112704

__device__ __forceinline__ float gelu_exact(float x) { return x * normcdff(x); }

// -------------------------------------------------------------------------
__global__ void transpose_x(const float* __restrict__ xs,
                            const float* __restrict__ xv) {
    const int p0 = blockIdx.x * 32;
    const int tx = threadIdx.x;   // 32
    const int ty = threadIdx.y;   // 8
    if (blockIdx.y == 0) {
        __shared__ float tile[32][33];
        #pragma unroll
        for (int r = ty; r < 32; r += 8) {
            int pp = p0 + tx;
            tile[r][tx] = (pp < PP) ? xs[r * PP + pp] : 0.f;
        }
        __syncthreads();
        #pragma unroll
        for (int r = ty; r < 32; r += 8) {
            int pp = p0 + r;
            if (pp < PP) g_xsT[pp * 32 + tx] = tile[tx][r];
        }
    } else {
        __shared__ float2 t2[16][33];
        const float2* xv2 = (const float2*)xv;
        #pragma unroll
        for (int r = ty; r < 16; r += 8) {
            int pp = p0 + tx;
            t2[r][tx] = (pp < PP) ? xv2[r * PP + pp] : make_float2(0.f, 0.f);
        }
        __syncthreads();
        const int tid = ty * 32 + tx;
        #pragma unroll
        for (int q = tid; q < 512; q += 256) {
            int i = q >> 4, v = q & 15;
            int pp = p0 + i;
            if (pp < PP) g_xvT2[pp * 16 + v] = t2[v][i];
        }
    }
}

// -------------------------------------------------------------------------
// Main: 192 threads, warp handles FOUR points; 24 pts per block-iteration.
// -------------------------------------------------------------------------
__global__ void __launch_bounds__(192, 2)
disco_main(const float* __restrict__ xs,  const float* __restrict__ xv,
           const int*   __restrict__ idx,
           const float* __restrict__ psi_ss, const float* __restrict__ psi_sv,
           const float* __restrict__ psi_vs, const float* __restrict__ psi_vv,
           const float* __restrict__ W_ss,  const float* __restrict__ W_vs,
           const float* __restrict__ W_sv,  const float* __restrict__ W_vv,
           const float* __restrict__ bias_s,
           const float* __restrict__ mlp_w1, const float* __restrict__ mlp_b1,
           const float* __restrict__ mlp_w2, const float* __restrict__ mlp_b2,
           const float* __restrict__ gate_w, const float* __restrict__ gate_b,
           float* __restrict__ out) {
    extern __shared__ float sm[];
    float4* smf4 = (float4*)sm;
    const int tid = threadIdx.x;

    // ---- stage W into float4-per-lane layouts ----
    {
        const float4* g = (const float4*)W_ss;     // o*32+i
        for (int t = tid; t < 1024; t += 192) { int o = t >> 5, i = t & 31; smf4[i * 32 + o] = g[t]; }
        g = (const float4*)W_vs;                   // o*16+i
        for (int t = tid; t < 512;  t += 192) { int o = t >> 4, i = t & 15; smf4[1024 + i * 32 + o] = g[t]; }
        g = (const float4*)W_sv;                   // o*32+i
        for (int t = tid; t < 512;  t += 192) { int o = t >> 5, i = t & 31; smf4[1536 + i * 16 + o] = g[t]; }
        g = (const float4*)W_vv;                   // o*16+i
        for (int t = tid; t < 256;  t += 192) { int o = t >> 4, i = t & 15; smf4[2048 + i * 16 + o] = g[t]; }
        g = (const float4*)mlp_w1;                 // j*8+i4
        for (int t = tid; t < 512;  t += 192) { int j = t >> 3, i4 = t & 7; smf4[2304 + i4 * 64 + j] = g[t]; }
        g = (const float4*)mlp_w2;                 // o*16+j4
        for (int t = tid; t < 512;  t += 192) { int o = t >> 4, j4 = t & 15; smf4[2816 + j4 * 32 + o] = g[t]; }
        g = (const float4*)gate_w;                 // v*8+i4
        for (int t = tid; t < 128;  t += 192) { int v = t >> 3, i4 = t & 7; smf4[3328 + i4 * 16 + v] = g[t]; }
        if (tid < 32) sm[BIAS_OFF + tid]       = bias_s[tid];
        if (tid < 64) sm[BIAS_OFF + 32 + tid]  = mlp_b1[tid];
        if (tid < 32) sm[BIAS_OFF + 96 + tid]  = mlp_b2[tid];
        if (tid < 16) sm[BIAS_OFF + 128 + tid] = gate_b[tid];
    }
    __syncthreads();

    const int warp = tid >> 5;       // 0..5
    const int lane = tid & 31;
    const int cc   = lane & 1;
    float* w = sm + WARP_OFF + warp * WSTRIDE;

    const float* xvTf = (const float*)g_xvT2;
    const float4* gss = (const float4*)psi_ss;
    const float4* gsv = (const float4*)psi_sv;
    const float4* gvs = (const float4*)psi_vs;
    const float4* gvv = (const float4*)psi_vv;

    for (int grp = blockIdx.x; grp < NG24; grp += gridDim.x) {
        const int p0 = grp * 24;

        // ================= z phase: four points sequentially ================
        #pragma unroll 1
        for (int q = 0; q < 4; q++) {
            const int p = p0 + (warp << 2) + q;
            float* zone = w + q * 592;

            // gather neighbors (coalesced 128B per neighbor)
            int jreg = (lane < 16) ? idx[p * 16 + lane] : 0;
            float xsg[16], xvg[16];
            #pragma unroll
            for (int n = 0; n < 16; n++) {
                int jn = __shfl_sync(FULLM, jreg, n);
                xsg[n] = g_xsT[jn * 32 + lane];
                xvg[n] = xvTf[jn * 32 + lane];
            }

            // stage psi into this point's slot
            float4* Pss4  = (float4*)(zone);
            float4* Psv4  = (float4*)(zone + 64);
            float2* PvsW2 = (float2*)(zone + 192);
            float2* PvvW2 = (float2*)(zone + 328);
            if (lane < 16) Pss4[lane] = gss[((lane >> 2) * PP + p) * 4 + (lane & 3)];
            Psv4[lane] = gsv[((lane >> 3) * PP + p) * 8 + (lane & 7)];
            {
                float4 f = gvs[((lane >> 3) * PP + p) * 8 + (lane & 7)];
                PvsW2[lane]      = make_float2(f.x, f.z);   // c=0
                PvsW2[34 + lane] = make_float2(f.y, f.w);   // c=1
            }
            #pragma unroll
            for (int it = 0; it < 2; it++) {
                int t = lane + it * 32;
                float4 f = gvv[((t >> 4) * PP + p) * 16 + (t & 15)];
                PvvW2[t]      = make_float2(f.x, f.z);      // d=0
                PvvW2[66 + t] = make_float2(f.y, f.w);      // d=1
            }
            __syncwarp();

            const float4* Pvs4 = (const float4*)(zone + 192);  // cc*17 + k*4+m
            const float4* Pvv4 = (const float4*)(zone + 328);  // cc*33 + k*8+m

            // ---- compute all z into registers ----
            float zssk[4], zsv0[4], zsv1[4], zvsk[4], zvv0[4], zvv1[4];
            #pragma unroll
            for (int k = 0; k < 4; k++) {
                float a = 0.f;
                #pragma unroll
                for (int m = 0; m < 4; m++) {
                    float4 qq = Pss4[k * 4 + m];
                    a += qq.x * xsg[4*m] + qq.y * xsg[4*m+1] + qq.z * xsg[4*m+2] + qq.w * xsg[4*m+3];
                }
                zssk[k] = a;
            }
            #pragma unroll
            for (int k = 0; k < 4; k++) {
                float a0 = 0.f, a1 = 0.f;
                #pragma unroll
                for (int m = 0; m < 8; m++) {
                    float4 qq = Psv4[k * 8 + m];
                    a0 += qq.x * xsg[2*m] + qq.z * xsg[2*m+1];
                    a1 += qq.y * xsg[2*m] + qq.w * xsg[2*m+1];
                }
                zsv0[k] = a0; zsv1[k] = a1;
            }
            #pragma unroll
            for (int k = 0; k < 4; k++) {
                float a = 0.f;
                #pragma unroll
                for (int m = 0; m < 4; m++) {
                    float4 qq = Pvs4[cc * 17 + k * 4 + m];
                    a += qq.x * xvg[4*m] + qq.y * xvg[4*m+1] + qq.z * xvg[4*m+2] + qq.w * xvg[4*m+3];
                }
                a += __shfl_xor_sync(FULLM, a, 1);
                zvsk[k] = a;
            }
            #pragma unroll
            for (int k = 0; k < 4; k++) {
                float a0 = 0.f, a1 = 0.f;
                #pragma unroll
                for (int m = 0; m < 8; m++) {
                    float4 qq = Pvv4[cc * 33 + k * 8 + m];
                    a0 += qq.x * xvg[2*m] + qq.z * xvg[2*m+1];
                    a1 += qq.y * xvg[2*m] + qq.w * xvg[2*m+1];
                }
                a0 += __shfl_xor_sync(FULLM, a0, 1);
                a1 += __shfl_xor_sync(FULLM, a1, 1);
                zvv0[k] = a0; zvv1[k] = a1;
            }
            __syncwarp();

            // ---- overwrite slot with z ----
            float4* Zss4 = (float4*)(zone);
            float4* Zvs4 = (float4*)(zone + 128);
            float4* Zsv4 = (float4*)(zone + 192);
            float4* Zvv4 = (float4*)(zone + 456);
            Zss4[lane]      = make_float4(zssk[0], zssk[1], zssk[2], zssk[3]);
            Zsv4[lane]      = make_float4(zsv0[0], zsv0[1], zsv0[2], zsv0[3]);
            Zsv4[33 + lane] = make_float4(zsv1[0], zsv1[1], zsv1[2], zsv1[3]);
            if (cc == 0) {
                Zvs4[lane >> 1]        = make_float4(zvsk[0], zvsk[1], zvsk[2], zvsk[3]);
                Zvv4[lane >> 1]        = make_float4(zvv0[0], zvv0[1], zvv0[2], zvv0[3]);
                Zvv4[17 + (lane >> 1)] = make_float4(zvv1[0], zvv1[1], zvv1[2], zvv1[3]);
            }
            __syncwarp();
        }

        // ================= W phase: four points share every W read ==========
        float4* Zf0 = (float4*)(w);
        float4* Zf1 = (float4*)(w + 592);
        float4* Zf2 = (float4*)(w + 1184);
        float4* Zf3 = (float4*)(w + 1776);

        // ---- s[o]: lane = o ----
        float acc0 = sm[BIAS_OFF + lane];
        float acc1 = acc0, acc2 = acc0, acc3 = acc0;
        #pragma unroll 4
        for (int i = 0; i < 32; i++) {
            float4 wv = smf4[i * 32 + lane];
            float4 zA = Zf0[i], zB = Zf1[i], zC = Zf2[i], zD = Zf3[i];
            acc0 += wv.x * zA.x + wv.y * zA.y + wv.z * zA.z + wv.w * zA.w;
            acc1 += wv.x * zB.x + wv.y * zB.y + wv.z * zB.z + wv.w * zB.w;
            acc2 += wv.x * zC.x + wv.y * zC.y + wv.z * zC.z + wv.w * zC.w;
            acc3 += wv.x * zD.x + wv.y * zD.y + wv.z * zD.z + wv.w * zD.w;
        }
        #pragma unroll 4
        for (int i = 0; i < 16; i++) {
            float4 wv = smf4[1024 + i * 32 + lane];
            float4 zA = Zf0[32 + i], zB = Zf1[32 + i], zC = Zf2[32 + i], zD = Zf3[32 + i];
            acc0 += wv.x * zA.x + wv.y * zA.y + wv.z * zA.z + wv.w * zA.w;
            acc1 += wv.x * zB.x + wv.y * zB.y + wv.z * zB.z + wv.w * zB.w;
            acc2 += wv.x * zC.x + wv.y * zC.y + wv.z * zC.z + wv.w * zC.w;
            acc3 += wv.x * zD.x + wv.y * zD.y + wv.z * zD.z + wv.w * zD.w;
        }
        float sg0 = gelu_exact(acc0), sg1 = gelu_exact(acc1);
        float sg2 = gelu_exact(acc2), sg3 = gelu_exact(acc3);

        // ---- v[o][c]: lane = c*16+o ----
        const int vc = lane >> 4, vo = lane & 15;
        float va0 = 0.f, va1 = 0.f, va2 = 0.f, va3 = 0.f;
        #pragma unroll 4
        for (int i = 0; i < 32; i++) {
            float4 wv = smf4[1536 + i * 16 + vo];
            float4 zA = Zf0[48 + vc * 33 + i], zB = Zf1[48 + vc * 33 + i];
            float4 zC = Zf2[48 + vc * 33 + i], zD = Zf3[48 + vc * 33 + i];
            va0 += wv.x * zA.x + wv.y * zA.y + wv.z * zA.z + wv.w * zA.w;
            va1 += wv.x * zB.x + wv.y * zB.y + wv.z * zB.z + wv.w * zB.w;
            va2 += wv.x * zC.x + wv.y * zC.y + wv.z * zC.z + wv.w * zC.w;
            va3 += wv.x * zD.x + wv.y * zD.y + wv.z * zD.z + wv.w * zD.w;
        }
        #pragma unroll 4
        for (int i = 0; i < 16; i++) {
            float4 wv = smf4[2048 + i * 16 + vo];
            float4 zA = Zf0[114 + vc * 17 + i], zB = Zf1[114 + vc * 17 + i];
            float4 zC = Zf2[114 + vc * 17 + i], zD = Zf3[114 + vc * 17 + i];
            va0 += wv.x * zA.x + wv.y * zA.y + wv.z * zA.z + wv.w * zA.w;
            va1 += wv.x * zB.x + wv.y * zB.y + wv.z * zB.z + wv.w * zB.w;
            va2 += wv.x * zC.x + wv.y * zC.y + wv.z * zC.z + wv.w * zC.w;
            va3 += wv.x * zD.x + wv.y * zD.y + wv.z * zD.z + wv.w * zD.w;
        }
        __syncwarp();

        // ---- write S (slots now fully consumed) ----
        (w + 0)[lane]    = sg0;
        (w + 592)[lane]  = sg1;
        (w + 1184)[lane] = sg2;
        (w + 1776)[lane] = sg3;
        __syncwarp();

        // ---- mlp hidden: lane does j=lane and j=lane+32, all 4 points ----
        {
            float b0 = sm[BIAS_OFF + 32 + lane];
            float b1 = sm[BIAS_OFF + 64 + lane];
            float h00 = b0, h01 = b0, h02 = b0, h03 = b0;
            float h10 = b1, h11 = b1, h12 = b1, h13 = b1;
            #pragma unroll
            for (int i4 = 0; i4 < 8; i4++) {
                float4 wa = smf4[2304 + i4 * 64 + lane];
                float4 wb = smf4[2304 + i4 * 64 + 32 + lane];
                float4 sA = Zf0[i4], sB = Zf1[i4], sC = Zf2[i4], sD = Zf3[i4];
                h00 += wa.x * sA.x + wa.y * sA.y + wa.z * sA.z + wa.w * sA.w;
                h01 += wa.x * sB.x + wa.y * sB.y + wa.z * sB.z + wa.w * sB.w;
                h02 += wa.x * sC.x + wa.y * sC.y + wa.z * sC.z + wa.w * sC.w;
                h03 += wa.x * sD.x + wa.y * sD.y + wa.z * sD.z + wa.w * sD.w;
                h10 += wb.x * sA.x + wb.y * sA.y + wb.z * sA.z + wb.w * sA.w;
                h11 += wb.x * sB.x + wb.y * sB.y + wb.z * sB.z + wb.w * sB.w;
                h12 += wb.x * sC.x + wb.y * sC.y + wb.z * sC.z + wb.w * sC.w;
                h13 += wb.x * sD.x + wb.y * sD.y + wb.z * sD.z + wb.w * sD.w;
            }
            __syncwarp();
            (w + 32)[lane]        = gelu_exact(h00);
            (w + 624)[lane]       = gelu_exact(h01);
            (w + 1216)[lane]      = gelu_exact(h02);
            (w + 1808)[lane]      = gelu_exact(h03);
            (w + 32)[lane + 32]   = gelu_exact(h10);
            (w + 624)[lane + 32]  = gelu_exact(h11);
            (w + 1216)[lane + 32] = gelu_exact(h12);
            (w + 1808)[lane + 32] = gelu_exact(h13);
        }
        __syncwarp();

        // ---- s_out[o]: lane = o ----
        {
            float b2v = sm[BIAS_OFF + 96 + lane];
            float a0 = sg0 + b2v, a1 = sg1 + b2v, a2 = sg2 + b2v, a3 = sg3 + b2v;
            #pragma unroll 8
            for (int j4 = 0; j4 < 16; j4++) {
                float4 wv = smf4[2816 + j4 * 32 + lane];
                float4 hA = Zf0[8 + j4], hB = Zf1[8 + j4], hC = Zf2[8 + j4], hD = Zf3[8 + j4];
                a0 += wv.x * hA.x + wv.y * hA.y + wv.z * hA.z + wv.w * hA.w;
                a1 += wv.x * hB.x + wv.y * hB.y + wv.z * hB.z + wv.w * hB.w;
                a2 += wv.x * hC.x + wv.y * hC.y + wv.z * hC.z + wv.w * hC.w;
                a3 += wv.x * hD.x + wv.y * hD.y + wv.z * hD.z + wv.w * hD.w;
            }
            __syncwarp();
            (w + 96)[lane]   = a0;
            (w + 688)[lane]  = a1;
            (w + 1280)[lane] = a2;
            (w + 1872)[lane] = a3;
        }
        __syncwarp();

        // ---- gate + final v: lane = c*16+o ----
        {
            float gb0 = sm[BIAS_OFF + 128 + vo];
            float g0 = gb0, g1 = gb0, g2 = gb0, g3 = gb0;
            #pragma unroll
            for (int i4 = 0; i4 < 8; i4++) {
                float4 wv = smf4[3328 + i4 * 16 + vo];
                float4 sA = Zf0[24 + i4], sB = Zf1[24 + i4], sC = Zf2[24 + i4], sD = Zf3[24 + i4];
                g0 += wv.x * sA.x + wv.y * sA.y + wv.z * sA.z + wv.w * sA.w;
                g1 += wv.x * sB.x + wv.y * sB.y + wv.z * sB.z + wv.w * sB.w;
                g2 += wv.x * sC.x + wv.y * sC.y + wv.z * sC.z + wv.w * sC.w;
                g3 += wv.x * sD.x + wv.y * sD.y + wv.z * sD.z + wv.w * sD.w;
            }
            (w + 128)[vo * 2 + vc]  = va0 * (1.f + g0);
            (w + 720)[vo * 2 + vc]  = va1 * (1.f + g1);
            (w + 1312)[vo * 2 + vc] = va2 * (1.f + g2);
            (w + 1904)[vo * 2 + vc] = va3 * (1.f + g3);
        }

        // ================= block epilogue: coalesced stores =================
        __syncthreads();
        #pragma unroll
        for (int rep = 0; rep < 4; rep++) {
            int qi = rep * 192 + tid;
            // scalar: 32 ch x 24 pts
            {
                int o = qi / 24, lp = qi % 24;
                int pp = p0 + lp;
                const float* so = sm + WARP_OFF + (lp >> 2) * WSTRIDE + (lp & 3) * 592 + 96;
                out[o * PP + pp] = xs[o * PP + pp] + so[o];
            }
            // vector: 16 ch x 24 pts x 2 comp
            {
                int v = qi / 48, r = qi % 48;
                int lpv = r >> 1, c2 = r & 1;
                const float* vv = sm + WARP_OFF + (lpv >> 2) * WSTRIDE + (lpv & 3) * 592 + 128;
                int voff = (v * PP + p0 + lpv) * 2 + c2;
                out[32 * PP + voff] = xv[voff] + vv[v * 2 + c2];
            }
        }
        __syncthreads();
    }
}

extern "C" void kernel_launch(void* const* d_in, const int* in_sizes, int n_in,
                              void* d_out, int out_size) {
    const bool dictOrder = (in_sizes[2] == PP * 16);
    const float* xs = (const float*)d_in[0];
    const float* xv = (const float*)d_in[1];
    const int base = dictOrder ? 3 : 2;
    const float* pss  = (const float*)d_in[base + 0];
    const float* psv  = (const float*)d_in[base + 1];
    const float* pvs  = (const float*)d_in[base + 2];
    const float* pvv  = (const float*)d_in[base + 3];
    const float* wss  = (const float*)d_in[base + 4];
    const float* wvs  = (const float*)d_in[base + 5];
    const float* wsv  = (const float*)d_in[base + 6];
    const float* wvv  = (const float*)d_in[base + 7];
    const float* bs   = (const float*)d_in[base + 8];
    const float* w1   = (const float*)d_in[base + 9];
    const float* b1   = (const float*)d_in[base + 10];
    const float* w2   = (const float*)d_in[base + 11];
    const float* b2   = (const float*)d_in[base + 12];
    const float* gw   = (const float*)d_in[base + 13];
    const float* gb   = (const float*)d_in[base + 14];
    const int*   idx  = (const int*)(dictOrder ? d_in[2] : d_in[17]);

    cudaFuncSetAttribute(disco_main, cudaFuncAttributeMaxDynamicSharedMemorySize, SMEM_BYTES);

    dim3 tb(32, 8);
    transpose_x<<<dim3((PP + 31) / 32, 2), tb>>>(xs, xv);
    disco_main<<<296, 192, SMEM_BYTES>>>(xs, xv, idx, pss, psv, pvs, pvv,
                                         wss, wvs, wsv, wvv, bs,
                                         w1, b1, w2, b2, gw, gb,
                                         (float*)d_out);
}

// round 7
// speedup vs baseline: 1.5535x; 1.0141x over previous
#include <cuda_runtime.h>
#include <math.h>

#define PP 65160              // H*W
#define FULLM 0xffffffffu

// scratch
__device__ float  g_xsT[PP * 32];
__device__ float2 g_xvT2[PP * 16];
__device__ float4 g_Z4[144 * PP];   // z features, [fq][p] float4 (k-packed), ~150 MB

__device__ __forceinline__ float gelu_exact(float x) { return x * normcdff(x); }

// -------------------------------------------------------------------------
// Transpose x_scalar (32,P)->(P,32) and x_vector (16,P,2)->(P,16) float2
// -------------------------------------------------------------------------
__global__ void transpose_x(const float* __restrict__ xs,
                            const float* __restrict__ xv) {
    const int p0 = blockIdx.x * 32;
    const int tx = threadIdx.x;   // 32
    const int ty = threadIdx.y;   // 8
    if (blockIdx.y == 0) {
        __shared__ float tile[32][33];
        #pragma unroll
        for (int r = ty; r < 32; r += 8) {
            int pp = p0 + tx;
            tile[r][tx] = (pp < PP) ? xs[r * PP + pp] : 0.f;
        }
        __syncthreads();
        #pragma unroll
        for (int r = ty; r < 32; r += 8) {
            int pp = p0 + r;
            if (pp < PP) g_xsT[pp * 32 + tx] = tile[tx][r];
        }
    } else {
        __shared__ float2 t2[16][33];
        const float2* xv2 = (const float2*)xv;
        #pragma unroll
        for (int r = ty; r < 16; r += 8) {
            int pp = p0 + tx;
            t2[r][tx] = (pp < PP) ? xv2[r * PP + pp] : make_float2(0.f, 0.f);
        }
        __syncthreads();
        const int tid = ty * 32 + tx;
        #pragma unroll
        for (int q = tid; q < 512; q += 256) {
            int i = q >> 4, v = q & 15;
            int pp = p0 + i;
            if (pp < PP) g_xvT2[pp * 16 + v] = t2[v][i];
        }
    }
}

// -------------------------------------------------------------------------
// Kernel A: z producer. 8 warps x 3 points = 24 pts/block, 2715 blocks exact.
// Tile: [fq 0..143][pl 0..23] float4, row pad 25. Then coalesced Z4 stores.
// fq map: 0..31 zss(i), 32..47 zvs(i), 48..79 zsv(c0,i), 80..111 zsv(c1,i),
//         112..127 zvv(c0,i), 128..143 zvv(c1,i)
// -------------------------------------------------------------------------
#define A_PSI_OFF 14400                      // floats (tile = 3600 f4)
#define A_SMEM_FLOATS (14400 + 8 * 592)      // 19136
#define A_SMEM_BYTES (A_SMEM_FLOATS * 4)     // 76544

__global__ void __launch_bounds__(256, 2)
disco_z(const int* __restrict__ idx,
        const float* __restrict__ psi_ss, const float* __restrict__ psi_sv,
        const float* __restrict__ psi_vs, const float* __restrict__ psi_vv) {
    extern __shared__ float sm[];
    float4* T4 = (float4*)sm;
    const int tid  = threadIdx.x;
    const int warp = tid >> 5;
    const int lane = tid & 31;
    const int cc   = lane & 1;
    float* zone = sm + A_PSI_OFF + warp * 592;

    const float* xvTf = (const float*)g_xvT2;
    const float4* gss = (const float4*)psi_ss;
    const float4* gsv = (const float4*)psi_sv;
    const float4* gvs = (const float4*)psi_vs;
    const float4* gvv = (const float4*)psi_vv;

    const int pbase = blockIdx.x * 24 + warp * 3;

    #pragma unroll 1
    for (int q = 0; q < 3; q++) {
        const int p  = pbase + q;
        const int pl = warp * 3 + q;

        // gather neighbors (coalesced 128B per neighbor)
        int jreg = (lane < 16) ? idx[p * 16 + lane] : 0;
        float xsg[16], xvg[16];
        #pragma unroll
        for (int n = 0; n < 16; n++) {
            int jn = __shfl_sync(FULLM, jreg, n);
            xsg[n] = g_xsT[jn * 32 + lane];
            xvg[n] = xvTf[jn * 32 + lane];
        }

        // stage psi into warp slot
        float4* Pss4  = (float4*)(zone);
        float4* Psv4  = (float4*)(zone + 64);
        float2* PvsW2 = (float2*)(zone + 192);
        float2* PvvW2 = (float2*)(zone + 328);
        if (lane < 16) Pss4[lane] = gss[((lane >> 2) * PP + p) * 4 + (lane & 3)];
        Psv4[lane] = gsv[((lane >> 3) * PP + p) * 8 + (lane & 7)];
        {
            float4 f = gvs[((lane >> 3) * PP + p) * 8 + (lane & 7)];
            PvsW2[lane]      = make_float2(f.x, f.z);   // c=0
            PvsW2[34 + lane] = make_float2(f.y, f.w);   // c=1
        }
        #pragma unroll
        for (int it = 0; it < 2; it++) {
            int t = lane + it * 32;
            float4 f = gvv[((t >> 4) * PP + p) * 16 + (t & 15)];
            PvvW2[t]      = make_float2(f.x, f.z);      // d=0
            PvvW2[66 + t] = make_float2(f.y, f.w);      // d=1
        }
        __syncwarp();

        const float4* Pvs4 = (const float4*)(zone + 192);  // cc*17 + k*4+m
        const float4* Pvv4 = (const float4*)(zone + 328);  // cc*33 + k*8+m

        // z into registers
        float zssk[4], zsv0[4], zsv1[4], zvsk[4], zvv0[4], zvv1[4];
        #pragma unroll
        for (int k = 0; k < 4; k++) {
            float a = 0.f;
            #pragma unroll
            for (int m = 0; m < 4; m++) {
                float4 qq = Pss4[k * 4 + m];
                a += qq.x * xsg[4*m] + qq.y * xsg[4*m+1] + qq.z * xsg[4*m+2] + qq.w * xsg[4*m+3];
            }
            zssk[k] = a;
        }
        #pragma unroll
        for (int k = 0; k < 4; k++) {
            float a0 = 0.f, a1 = 0.f;
            #pragma unroll
            for (int m = 0; m < 8; m++) {
                float4 qq = Psv4[k * 8 + m];
                a0 += qq.x * xsg[2*m] + qq.z * xsg[2*m+1];
                a1 += qq.y * xsg[2*m] + qq.w * xsg[2*m+1];
            }
            zsv0[k] = a0; zsv1[k] = a1;
        }
        #pragma unroll
        for (int k = 0; k < 4; k++) {
            float a = 0.f;
            #pragma unroll
            for (int m = 0; m < 4; m++) {
                float4 qq = Pvs4[cc * 17 + k * 4 + m];
                a += qq.x * xvg[4*m] + qq.y * xvg[4*m+1] + qq.z * xvg[4*m+2] + qq.w * xvg[4*m+3];
            }
            a += __shfl_xor_sync(FULLM, a, 1);
            zvsk[k] = a;
        }
        #pragma unroll
        for (int k = 0; k < 4; k++) {
            float a0 = 0.f, a1 = 0.f;
            #pragma unroll
            for (int m = 0; m < 8; m++) {
                float4 qq = Pvv4[cc * 33 + k * 8 + m];
                a0 += qq.x * xvg[2*m] + qq.z * xvg[2*m+1];
                a1 += qq.y * xvg[2*m] + qq.w * xvg[2*m+1];
            }
            a0 += __shfl_xor_sync(FULLM, a0, 1);
            a1 += __shfl_xor_sync(FULLM, a1, 1);
            zvv0[k] = a0; zvv1[k] = a1;
        }

        // store into tile (conflict-free STS.128, 400B lane stride)
        T4[lane * 25 + pl]        = make_float4(zssk[0], zssk[1], zssk[2], zssk[3]);
        T4[(48 + lane) * 25 + pl] = make_float4(zsv0[0], zsv0[1], zsv0[2], zsv0[3]);
        T4[(80 + lane) * 25 + pl] = make_float4(zsv1[0], zsv1[1], zsv1[2], zsv1[3]);
        if (cc == 0) {
            int i = lane >> 1;
            T4[(32 + i) * 25 + pl]  = make_float4(zvsk[0], zvsk[1], zvsk[2], zvsk[3]);
            T4[(112 + i) * 25 + pl] = make_float4(zvv0[0], zvv0[1], zvv0[2], zvv0[3]);
            T4[(128 + i) * 25 + pl] = make_float4(zvv1[0], zvv1[1], zvv1[2], zvv1[3]);
        }
        __syncwarp();   // slot reuse next q
    }

    // coalesced tile -> global
    __syncthreads();
    const int p0 = blockIdx.x * 24;
    for (int t = tid; t < 144 * 24; t += 256) {
        int fq = t / 24, pl = t % 24;
        g_Z4[fq * PP + p0 + pl] = T4[fq * 25 + pl];
    }
}

// -------------------------------------------------------------------------
// Kernel B: GEMM chain, lane = point. 255 blocks x 256 threads, 1 wave.
// smem: f4[0..1536) WS [fq][o:32]; f4[1536..2304) WV [i-row][o:16];
//       f4[2304..2816) W1 [j][i4]; f4[2816..3328) W2 [o][j4];
//       f4[3328..3456) GW [v][i4]; floats 13824..13968 biases.
// -------------------------------------------------------------------------
#define B_BIAS 13824
#define B_SMEM_BYTES (3456 * 16 + 576)

__global__ void __launch_bounds__(256, 2)
disco_w(const float* __restrict__ xs, const float* __restrict__ xv,
        const float* __restrict__ W_ss, const float* __restrict__ W_vs,
        const float* __restrict__ W_sv, const float* __restrict__ W_vv,
        const float* __restrict__ bias_s,
        const float* __restrict__ mlp_w1, const float* __restrict__ mlp_b1,
        const float* __restrict__ mlp_w2, const float* __restrict__ mlp_b2,
        const float* __restrict__ gate_w, const float* __restrict__ gate_b,
        float* __restrict__ out) {
    extern __shared__ float sm[];
    float4* s4 = (float4*)sm;
    const int tid = threadIdx.x;

    // stage W
    {
        const float4* g = (const float4*)W_ss;    // f4 idx o*32+i
        for (int t = tid; t < 1024; t += 256) { int o = t >> 5, i = t & 31; s4[i * 32 + o] = g[t]; }
        g = (const float4*)W_vs;                  // o*16+i
        for (int t = tid; t < 512;  t += 256) { int o = t >> 4, i = t & 15; s4[(32 + i) * 32 + o] = g[t]; }
        g = (const float4*)W_sv;                  // o*32+i
        for (int t = tid; t < 512;  t += 256) { int o = t >> 5, i = t & 31; s4[1536 + i * 16 + o] = g[t]; }
        g = (const float4*)W_vv;                  // o*16+i
        for (int t = tid; t < 256;  t += 256) { int o = t >> 4, i = t & 15; s4[1536 + (32 + i) * 16 + o] = g[t]; }
        g = (const float4*)mlp_w1;
        for (int t = tid; t < 512;  t += 256) s4[2304 + t] = g[t];
        g = (const float4*)mlp_w2;
        for (int t = tid; t < 512;  t += 256) s4[2816 + t] = g[t];
        g = (const float4*)gate_w;
        for (int t = tid; t < 128;  t += 256) s4[3328 + t] = g[t];
        if (tid < 32) sm[B_BIAS + tid]       = bias_s[tid];
        if (tid < 64) sm[B_BIAS + 32 + tid]  = mlp_b1[tid];
        if (tid < 32) sm[B_BIAS + 96 + tid]  = mlp_b2[tid];
        if (tid < 16) sm[B_BIAS + 128 + tid] = gate_b[tid];
    }
    __syncthreads();

    const int p  = blockIdx.x * 256 + tid;
    const int pc = (p < PP) ? p : (PP - 1);

    // ---- phase S: s[o] = gelu(bias + WS . z) ----
    float acc[32];
    #pragma unroll
    for (int o = 0; o < 32; o++) acc[o] = sm[B_BIAS + o];
    #pragma unroll 2
    for (int f = 0; f < 48; f++) {
        float4 z = g_Z4[f * PP + pc];
        const float4* wrow = s4 + f * 32;
        #pragma unroll
        for (int o = 0; o < 32; o++) {
            float4 wv = wrow[o];
            acc[o] += wv.x * z.x + wv.y * z.y + wv.z * z.z + wv.w * z.w;
        }
    }
    #pragma unroll
    for (int o = 0; o < 32; o++) acc[o] = gelu_exact(acc[o]);   // acc = s

    // ---- MLP: so = s + b2 + W2 . gelu(W1 . s + b1) ----
    float so[32];
    #pragma unroll
    for (int o = 0; o < 32; o++) so[o] = acc[o] + sm[B_BIAS + 96 + o];
    #pragma unroll 1
    for (int j4 = 0; j4 < 16; j4++) {
        float h[4];
        #pragma unroll
        for (int jj = 0; jj < 4; jj++) {
            int j = j4 * 4 + jj;
            float a = sm[B_BIAS + 32 + j];
            #pragma unroll
            for (int i4 = 0; i4 < 8; i4++) {
                float4 wv = s4[2304 + j * 8 + i4];
                a += wv.x * acc[i4*4] + wv.y * acc[i4*4+1] + wv.z * acc[i4*4+2] + wv.w * acc[i4*4+3];
            }
            h[jj] = gelu_exact(a);
        }
        #pragma unroll
        for (int o = 0; o < 32; o++) {
            float4 wv = s4[2816 + o * 16 + j4];
            so[o] += wv.x * h[0] + wv.y * h[1] + wv.z * h[2] + wv.w * h[3];
        }
    }

    // ---- gate: g = 1 + gb + GW . so ----
    float gte[16];
    #pragma unroll
    for (int v = 0; v < 16; v++) {
        float a = sm[B_BIAS + 128 + v];
        #pragma unroll
        for (int i4 = 0; i4 < 8; i4++) {
            float4 wv = s4[3328 + v * 8 + i4];
            a += wv.x * so[i4*4] + wv.y * so[i4*4+1] + wv.z * so[i4*4+2] + wv.w * so[i4*4+3];
        }
        gte[v] = 1.f + a;
    }

    // ---- scalar output ----
    if (p < PP) {
        #pragma unroll
        for (int o = 0; o < 32; o++) out[o * PP + p] = xs[o * PP + p] + so[o];
    }

    // ---- phase V: v[o][c] then gated vector output ----
    float vx[16], vy[16];
    #pragma unroll
    for (int o = 0; o < 16; o++) { vx[o] = 0.f; vy[o] = 0.f; }
    #pragma unroll 2
    for (int i = 0; i < 32; i++) {
        float4 z0 = g_Z4[(48 + i) * PP + pc];
        float4 z1 = g_Z4[(80 + i) * PP + pc];
        const float4* wrow = s4 + 1536 + i * 16;
        #pragma unroll
        for (int o = 0; o < 16; o++) {
            float4 wv = wrow[o];
            vx[o] += wv.x * z0.x + wv.y * z0.y + wv.z * z0.z + wv.w * z0.w;
            vy[o] += wv.x * z1.x + wv.y * z1.y + wv.z * z1.z + wv.w * z1.w;
        }
    }
    #pragma unroll 2
    for (int i = 0; i < 16; i++) {
        float4 z0 = g_Z4[(112 + i) * PP + pc];
        float4 z1 = g_Z4[(128 + i) * PP + pc];
        const float4* wrow = s4 + 1536 + (32 + i) * 16;
        #pragma unroll
        for (int o = 0; o < 16; o++) {
            float4 wv = wrow[o];
            vx[o] += wv.x * z0.x + wv.y * z0.y + wv.z * z0.z + wv.w * z0.w;
            vy[o] += wv.x * z1.x + wv.y * z1.y + wv.z * z1.z + wv.w * z1.w;
        }
    }
    if (p < PP) {
        const float2* xv2 = (const float2*)xv;
        float2* outv = (float2*)(out + 32 * PP);
        #pragma unroll
        for (int o = 0; o < 16; o++) {
            float2 b = xv2[o * PP + p];
            outv[o * PP + p] = make_float2(b.x + vx[o] * gte[o], b.y + vy[o] * gte[o]);
        }
    }
}

extern "C" void kernel_launch(void* const* d_in, const int* in_sizes, int n_in,
                              void* d_out, int out_size) {
    const bool dictOrder = (in_sizes[2] == PP * 16);
    const float* xs = (const float*)d_in[0];
    const float* xv = (const float*)d_in[1];
    const int base = dictOrder ? 3 : 2;
    const float* pss  = (const float*)d_in[base + 0];
    const float* psv  = (const float*)d_in[base + 1];
    const float* pvs  = (const float*)d_in[base + 2];
    const float* pvv  = (const float*)d_in[base + 3];
    const float* wss  = (const float*)d_in[base + 4];
    const float* wvs  = (const float*)d_in[base + 5];
    const float* wsv  = (const float*)d_in[base + 6];
    const float* wvv  = (const float*)d_in[base + 7];
    const float* bs   = (const float*)d_in[base + 8];
    const float* w1   = (const float*)d_in[base + 9];
    const float* b1   = (const float*)d_in[base + 10];
    const float* w2   = (const float*)d_in[base + 11];
    const float* b2   = (const float*)d_in[base + 12];
    const float* gw   = (const float*)d_in[base + 13];
    const float* gb   = (const float*)d_in[base + 14];
    const int*   idx  = (const int*)(dictOrder ? d_in[2] : d_in[17]);

    cudaFuncSetAttribute(disco_z, cudaFuncAttributeMaxDynamicSharedMemorySize, A_SMEM_BYTES);
    cudaFuncSetAttribute(disco_w, cudaFuncAttributeMaxDynamicSharedMemorySize, B_SMEM_BYTES);

    dim3 tb(32, 8);
    transpose_x<<<dim3((PP + 31) / 32, 2), tb>>>(xs, xv);
    disco_z<<<2715, 256, A_SMEM_BYTES>>>(idx, pss, psv, pvs, pvv);
    disco_w<<<255, 256, B_SMEM_BYTES>>>(xs, xv, wss, wvs, wsv, wvv, bs,
                                        w1, b1, w2, b2, gw, gb, (float*)d_out);
}